// round 16
// baseline (speedup 1.0000x reference)
#include <cuda_runtime.h>
#include <cuda_fp16.h>
#include <math.h>
#include <stdint.h>

#define BT    8192      // B*T tokens
#define DDIM  1024
#define WRD   128
#define KF    1152      // D + WR
#define HDIM  4096
#define NPATH 5
#define ZD    5120      // NPATH * D

// ---------------- scratch (device globals; allocation-free) ----------------
__device__ __half g_abuf[BT * KF];                // LN(cat(x, r_feat)), fp16
__device__ __half g_hbuf[BT * HDIM];              // gelu(A@W1 + b1), fp16
__device__ __half g_vtp [BT * DDIM];              // vt + h@W2 + b2 (fp16)
__device__ __half g_w1h [KF * HDIM];              // w1 fp16 [K,N]
__device__ __half g_w2h [HDIM * DDIM];            // w2 fp16 [K,N]
__device__ float  g_gwg [NPATH * ZD];             // (pg_g * gate_w)^T [5, 5120] fp32
__device__ float  g_gcp [20 * 10];                // per-block partials of c1[5], c2[5]

// ---------------- helpers ----------------
__device__ __forceinline__ float tanh_fast(float x) {
    float t;
    asm("tanh.approx.f32 %0, %1;" : "=f"(t) : "f"(x));
    return t;
}
__device__ __forceinline__ float gelu_tanh(float v) {
    float t = tanh_fast(0.7978845608028654f * (v + 0.044715f * v * v * v));
    return 0.5f * v * (1.0f + t);
}
__device__ __forceinline__ uint32_t smem_u32(const void* p) {
    uint32_t a;
    asm("{ .reg .u64 t; cvta.to.shared.u64 t, %1; cvt.u32.u64 %0, t; }" : "=r"(a) : "l"(p));
    return a;
}
__device__ __forceinline__ void mma_f16(float* d, const uint32_t* a, const uint32_t* b) {
    asm volatile(
        "mma.sync.aligned.m16n8k16.row.col.f32.f16.f16.f32 "
        "{%0,%1,%2,%3}, {%4,%5,%6,%7}, {%8,%9}, {%0,%1,%2,%3};"
        : "+f"(d[0]), "+f"(d[1]), "+f"(d[2]), "+f"(d[3])
        : "r"(a[0]), "r"(a[1]), "r"(a[2]), "r"(a[3]),
          "r"(b[0]), "r"(b[1]));
}
__device__ __forceinline__ void ldsm_x4(uint32_t* r, uint32_t addr) {
    asm volatile("ldmatrix.sync.aligned.m8n8.x4.shared.b16 {%0,%1,%2,%3}, [%4];"
        : "=r"(r[0]), "=r"(r[1]), "=r"(r[2]), "=r"(r[3]) : "r"(addr));
}
__device__ __forceinline__ void ldsm_x4_t(uint32_t* r, uint32_t addr) {
    asm volatile("ldmatrix.sync.aligned.m8n8.x4.trans.shared.b16 {%0,%1,%2,%3}, [%4];"
        : "=r"(r[0]), "=r"(r[1]), "=r"(r[2]), "=r"(r[3]) : "r"(addr));
}
__device__ __forceinline__ void cp16(uint32_t dst, const void* src) {
    asm volatile("cp.async.cg.shared.global [%0], [%1], 16;" :: "r"(dst), "l"(src));
}
__device__ __forceinline__ void cp_commit() {
    asm volatile("cp.async.commit_group;" ::: "memory");
}
template <int N>
__device__ __forceinline__ void cp_wait() {
    asm volatile("cp.async.wait_group %0;" :: "n"(N) : "memory");
}

// ---------------- K0: merged pre-kernel -----------------------------------------------
#define N1F4 (KF * HDIM / 4)
#define N2F4 (HDIM * DDIM / 4)
#define NB_W ((N1F4 + N2F4) / 256)       // 8704 (exact)
#define NB_G 20                          // ZD / 256
#define LTOK 4
#define NB_L (BT / LTOK)                 // 2048
#define NB_PRE (NB_W + NB_G + NB_L)

__global__ __launch_bounds__(256)
void pre_kernel(const float* __restrict__ w1, __half* __restrict__ w1h,
                const float* __restrict__ w2, __half* __restrict__ w2h,
                const float* __restrict__ gw, const float* __restrict__ pg_g,
                const float* __restrict__ pg_b, float* __restrict__ gwg,
                float* __restrict__ gcp,
                const float* __restrict__ x, const float* __restrict__ rf,
                const float* __restrict__ g, const float* __restrict__ b,
                __half* __restrict__ out) {
    const int blk = blockIdx.x;
    const int tid = threadIdx.x;

    if (blk < NB_W) {
        int i = blk * 256 + tid;
        const float4* src;
        uint2* dst;
        int idx;
        if (i < N1F4) { src = (const float4*)w1; dst = (uint2*)w1h; idx = i; }
        else          { src = (const float4*)w2; dst = (uint2*)w2h; idx = i - N1F4; }
        float4 v = src[idx];
        __half2 h01 = __floats2half2_rn(v.x, v.y);
        __half2 h23 = __floats2half2_rn(v.z, v.w);
        uint2 o;
        o.x = *reinterpret_cast<uint32_t*>(&h01);
        o.y = *reinterpret_cast<uint32_t*>(&h23);
        dst[idx] = o;
        return;
    }
    if (blk < NB_W + NB_G) {
        __shared__ float red[8][10];
        int kblk = blk - NB_W;
        int k = kblk * 256 + tid;
        float gk = pg_g[k], bk = pg_b[k];
        float c1l[NPATH], c2l[NPATH];
        #pragma unroll
        for (int p = 0; p < NPATH; p++) {
            float w = gw[(size_t)k * NPATH + p];
            float gg = gk * w;
            gwg[p * ZD + k] = gg;
            c1l[p] = gg;
            c2l[p] = bk * w;
        }
        int lane = tid & 31, wp = tid >> 5;
        #pragma unroll
        for (int p = 0; p < NPATH; p++) {
            #pragma unroll
            for (int o = 16; o > 0; o >>= 1) {
                c1l[p] += __shfl_down_sync(0xffffffffu, c1l[p], o);
                c2l[p] += __shfl_down_sync(0xffffffffu, c2l[p], o);
            }
        }
        if (lane == 0) {
            #pragma unroll
            for (int p = 0; p < NPATH; p++) {
                red[wp][p] = c1l[p];
                red[wp][p + NPATH] = c2l[p];
            }
        }
        __syncthreads();
        if (tid < 10) {
            float a = 0.f;
            #pragma unroll
            for (int ww = 0; ww < 8; ww++) a += red[ww][tid];
            gcp[kblk * 10 + tid] = a;
        }
        return;
    }

    // LN region: 4 tokens per block
    {
        const int t0 = (blk - NB_W - NB_G) * LTOK;
        __shared__ float red8[8][8];
        __shared__ float musm[LTOK], rssm[LTOK];
        const int lane = tid & 31, w = tid >> 5;
        const float4* x4  = (const float4*)x;
        const float4* rf4 = (const float4*)rf;
        const float4* g4  = (const float4*)g;
        const float4* b4  = (const float4*)b;
        const bool has2 = tid < 32;

        float4 gg0 = g4[tid], bb0 = b4[tid];
        float4 gg1, bb1;
        if (has2) { gg1 = g4[256 + tid]; bb1 = b4[256 + tid]; }

        float4 v0[LTOK], v1[LTOK];
        float ls[LTOK], lq[LTOK];
        #pragma unroll
        for (int tok = 0; tok < LTOK; tok++) {
            int t = t0 + tok;
            float4 a = x4[(size_t)t * 256 + tid];
            v0[tok] = a;
            float s = a.x + a.y + a.z + a.w;
            float q = a.x * a.x + a.y * a.y + a.z * a.z + a.w * a.w;
            if (has2) {
                float4 c = rf4[(size_t)t * 32 + tid];
                v1[tok] = c;
                s += c.x + c.y + c.z + c.w;
                q += c.x * c.x + c.y * c.y + c.z * c.z + c.w * c.w;
            }
            ls[tok] = s; lq[tok] = q;
        }
        #pragma unroll
        for (int tok = 0; tok < LTOK; tok++) {
            #pragma unroll
            for (int o = 16; o > 0; o >>= 1) {
                ls[tok] += __shfl_down_sync(0xffffffffu, ls[tok], o);
                lq[tok] += __shfl_down_sync(0xffffffffu, lq[tok], o);
            }
        }
        if (lane == 0) {
            #pragma unroll
            for (int tok = 0; tok < LTOK; tok++) {
                red8[w][tok] = ls[tok];
                red8[w][tok + 4] = lq[tok];
            }
        }
        __syncthreads();
        if (tid < 8) {
            float a = 0.f;
            #pragma unroll
            for (int ww = 0; ww < 8; ww++) a += red8[ww][tid];
            if (tid < 4) musm[tid] = a * (1.0f / KF);
            else         red8[0][tid] = a;
        }
        __syncthreads();
        if (tid < 4) {
            float mu = musm[tid];
            rssm[tid] = rsqrtf(red8[0][tid + 4] * (1.0f / KF) - mu * mu + 1e-5f);
        }
        __syncthreads();

        uint2* o4 = (uint2*)out;
        #pragma unroll
        for (int tok = 0; tok < LTOK; tok++) {
            float mu = musm[tok], rs = rssm[tok];
            float4 a = v0[tok];
            __half2 h01 = __floats2half2_rn((a.x - mu) * rs * gg0.x + bb0.x,
                                            (a.y - mu) * rs * gg0.y + bb0.y);
            __half2 h23 = __floats2half2_rn((a.z - mu) * rs * gg0.z + bb0.z,
                                            (a.w - mu) * rs * gg0.w + bb0.w);
            uint2 o;
            o.x = *reinterpret_cast<uint32_t*>(&h01);
            o.y = *reinterpret_cast<uint32_t*>(&h23);
            o4[(size_t)(t0 + tok) * (KF / 4) + tid] = o;
            if (has2) {
                float4 c = v1[tok];
                __half2 k01 = __floats2half2_rn((c.x - mu) * rs * gg1.x + bb1.x,
                                                (c.y - mu) * rs * gg1.y + bb1.y);
                __half2 k23 = __floats2half2_rn((c.z - mu) * rs * gg1.z + bb1.z,
                                                (c.w - mu) * rs * gg1.w + bb1.w);
                uint2 o2;
                o2.x = *reinterpret_cast<uint32_t*>(&k01);
                o2.y = *reinterpret_cast<uint32_t*>(&k23);
                o4[(size_t)(t0 + tok) * (KF / 4) + 256 + tid] = o2;
            }
        }
    }
}

// ---------------- fp16 mma.sync GEMM: CTA 128x128, warp 64x32, BK=64 ------------------
#define TS_H   72
#define TS_B   136
#define A_TILE_B (128 * TS_H * 2)
#define B_TILE_B (64 * TS_B * 2)
#define ST_B   (A_TILE_B + B_TILE_B)
#define NSTAGE 3
#define GEMM_SMEM (NSTAGE * ST_B)

__device__ __forceinline__ void load_a_tile(const __half* __restrict__ g, int row0, int K,
                                            int kt, uint32_t sm) {
    int tid = threadIdx.x;
    #pragma unroll
    for (int i = 0; i < 4; i++) {
        int lin = tid + i * 256;
        int row = lin >> 3, c8 = lin & 7;
        cp16(sm + (uint32_t)(row * TS_H + c8 * 8) * 2,
             &g[(size_t)(row0 + row) * K + kt + c8 * 8]);
    }
}
__device__ __forceinline__ void load_b_tile(const __half* __restrict__ g, int nb, int N,
                                            int kt, uint32_t sm) {
    int tid = threadIdx.x;
    #pragma unroll
    for (int i = 0; i < 4; i++) {
        int lin = tid + i * 256;
        int row = lin >> 4, c16 = lin & 15;
        cp16(sm + (uint32_t)(row * TS_B + c16 * 8) * 2,
             &g[(size_t)(kt + row) * N + nb + c16 * 8]);
    }
}

template <int EPI>
__global__ __launch_bounds__(256, 2)
void gemm_f16_kernel(const __half* __restrict__ A, const __half* __restrict__ Bkn,
                     const float* __restrict__ bias, const float* __restrict__ resid,
                     __half* __restrict__ Cout, int M, int N, int K) {
    extern __shared__ __half smh[];
    uint32_t sbase = smem_u32(smh);

    const int tid  = threadIdx.x;
    const int lane = tid & 31;
    const int warp = tid >> 5;
    const int wm = warp >> 2;
    const int wn = warp & 3;
    const int mb = blockIdx.y * 128;
    const int nb = blockIdx.x * 128;
    const int r = lane >> 2;
    const int c = lane & 3;

    uint32_t offA[4], offB[2];
    #pragma unroll
    for (int mi = 0; mi < 4; mi++) {
        int row = wm * 64 + mi * 16 + (lane & 15);
        offA[mi] = (uint32_t)(row * TS_H + ((lane >> 4) & 1) * 8) * 2;
    }
    #pragma unroll
    for (int np = 0; np < 2; np++) {
        int krow = ((lane >> 3) & 1) * 8 + (lane & 7);
        int ncol = wn * 32 + np * 16 + ((lane >> 4) & 1) * 8;
        offB[np] = (uint32_t)(krow * TS_B + ncol) * 2;
    }

    float acc[4][4][4];
    #pragma unroll
    for (int mi = 0; mi < 4; mi++)
        #pragma unroll
        for (int ni = 0; ni < 4; ni++)
            #pragma unroll
            for (int j = 0; j < 4; j++) acc[mi][ni][j] = 0.0f;

    const int S = K >> 6;

    load_a_tile(A,   mb, K, 0, sbase);
    load_b_tile(Bkn, nb, N, 0, sbase + A_TILE_B);
    cp_commit();
    if (S > 1) {
        load_a_tile(A,   mb, K, 64, sbase + ST_B);
        load_b_tile(Bkn, nb, N, 64, sbase + ST_B + A_TILE_B);
    }
    cp_commit();

    int p = 0;
    for (int s = 0; s < S; s++) {
        if (s < S - 1) cp_wait<1>(); else cp_wait<0>();
        __syncthreads();

        if (s + 2 < S) {
            int q = p + 2; if (q >= NSTAGE) q -= NSTAGE;
            load_a_tile(A,   mb, K, (s + 2) << 6, sbase + q * ST_B);
            load_b_tile(Bkn, nb, N, (s + 2) << 6, sbase + q * ST_B + A_TILE_B);
        }
        cp_commit();

        uint32_t abase = sbase + p * ST_B;
        uint32_t bbase = abase + A_TILE_B;

        #pragma unroll
        for (int kk = 0; kk < 4; kk++) {
            uint32_t koffA = (uint32_t)kk * 32;
            uint32_t koffB = (uint32_t)kk * (16 * TS_B * 2);
            uint32_t afr[4][4];
            uint32_t bfr[2][4];
            #pragma unroll
            for (int mi = 0; mi < 4; mi++) ldsm_x4(afr[mi], abase + offA[mi] + koffA);
            #pragma unroll
            for (int np = 0; np < 2; np++) ldsm_x4_t(bfr[np], bbase + offB[np] + koffB);
            #pragma unroll
            for (int mi = 0; mi < 4; mi++)
                #pragma unroll
                for (int ni = 0; ni < 4; ni++)
                    mma_f16(acc[mi][ni], afr[mi], &bfr[ni >> 1][(ni & 1) * 2]);
        }
        p++; if (p >= NSTAGE) p -= NSTAGE;
    }
    __syncthreads();

    #pragma unroll
    for (int mi = 0; mi < 4; mi++) {
        int row0 = mb + wm * 64 + mi * 16 + r;
        #pragma unroll
        for (int ni = 0; ni < 4; ni++) {
            int col0 = nb + wn * 32 + ni * 8 + 2 * c;
            float bs0 = bias[col0], bs1 = bias[col0 + 1];
            #pragma unroll
            for (int half = 0; half < 2; half++) {
                int row = row0 + half * 8;
                float v0 = acc[mi][ni][half * 2 + 0] + bs0;
                float v1 = acc[mi][ni][half * 2 + 1] + bs1;
                __half2 hv;
                if (EPI == 0) {
                    hv = __floats2half2_rn(gelu_tanh(v0), gelu_tanh(v1));
                } else {
                    float2 rv = *reinterpret_cast<const float2*>(&resid[(size_t)row * N + col0]);
                    hv = __floats2half2_rn(v0 + rv.x, v1 + rv.y);
                }
                *reinterpret_cast<__half2*>(&Cout[(size_t)row * N + col0]) = hv;
            }
        }
    }
}

// ---------------- K3: path gating, folded-LN logits, register-dieted ------------------
#define GTOK 4
#define GTHR 256
#define Z4PT (ZD / 4)
__global__ __launch_bounds__(GTHR, 4)
void gate_kernel(const __half* __restrict__ vtp, const float* __restrict__ dts,
                 const float* __restrict__ gwg, const float* __restrict__ gcp,
                 const float* __restrict__ gb,
                 float* __restrict__ out, float* __restrict__ gmem_out) {
    extern __shared__ uint2 z2s[];           // [GTOK][Z4PT] fp16x4 = 40 KB
    __shared__ float red[8][28];             // [warp][tok*7 + stat]
    __shared__ float vals[28];
    __shared__ float csm[10];                // c1[5], c2[5]
    __shared__ float spi[GTOK][NPATH];

    const int tid = threadIdx.x;
    const int lane = tid & 31;
    const int w = tid >> 5;
    const int t0 = blockIdx.x * GTOK;

    const uint2*  vtp2 = (const uint2*)vtp;      // 4 halfs per uint2
    const float4* dts4 = (const float4*)dts;
    const float4* gwg4 = (const float4*)gwg;     // [5][Z4PT]

    float st[GTOK][7];   // [tok][0]=sum [1]=sq [2..6]=dot_p
    #pragma unroll
    for (int tok = 0; tok < GTOK; tok++)
        #pragma unroll
        for (int j = 0; j < 7; j++) st[tok][j] = 0.f;

    // single pass: load z (all 4 tokens live) -> fp16 smem, stats, then per-path dots
    for (int i4 = tid; i4 < Z4PT; i4 += GTHR) {
        int p = i4 >> 8, d4 = i4 & 255;
        float4 v[GTOK];
        #pragma unroll
        for (int tok = 0; tok < GTOK; tok++) {
            int t = t0 + tok;
            uint2 zc;
            if (p == 0) {
                zc = vtp2[(size_t)t * 256 + d4];
                __half2 h01 = *reinterpret_cast<__half2*>(&zc.x);
                __half2 h23 = *reinterpret_cast<__half2*>(&zc.y);
                float2 f01 = __half22float2(h01);
                float2 f23 = __half22float2(h23);
                v[tok] = make_float4(f01.x, f01.y, f23.x, f23.y);
            } else {
                v[tok] = dts4[((size_t)(p - 1) * BT + t) * 256 + d4];
                __half2 h01 = __floats2half2_rn(v[tok].x, v[tok].y);
                __half2 h23 = __floats2half2_rn(v[tok].z, v[tok].w);
                zc.x = *reinterpret_cast<uint32_t*>(&h01);
                zc.y = *reinterpret_cast<uint32_t*>(&h23);
            }
            z2s[tok * Z4PT + i4] = zc;
            st[tok][0] += v[tok].x + v[tok].y + v[tok].z + v[tok].w;
            st[tok][1] += v[tok].x * v[tok].x + v[tok].y * v[tok].y
                        + v[tok].z * v[tok].z + v[tok].w * v[tok].w;
        }
        #pragma unroll
        for (int pp = 0; pp < NPATH; pp++) {
            float4 gwf = gwg4[pp * Z4PT + i4];
            #pragma unroll
            for (int tok = 0; tok < GTOK; tok++)
                st[tok][2 + pp] += v[tok].x * gwf.x + v[tok].y * gwf.y
                                 + v[tok].z * gwf.z + v[tok].w * gwf.w;
        }
    }
    // warp reduce all 28
    #pragma unroll
    for (int tok = 0; tok < GTOK; tok++)
        #pragma unroll
        for (int j = 0; j < 7; j++) {
            float v = st[tok][j];
            #pragma unroll
            for (int o = 16; o > 0; o >>= 1) v += __shfl_down_sync(0xffffffffu, v, o);
            if (lane == 0) red[w][tok * 7 + j] = v;
        }
    __syncthreads();
    if (tid < 28) {
        float a = 0.f;
        #pragma unroll
        for (int ww = 0; ww < 8; ww++) a += red[ww][tid];
        vals[tid] = a;
    }
    if (tid >= 32 && tid < 42) {
        int j = tid - 32;
        float a = 0.f;
        #pragma unroll
        for (int kb = 0; kb < 20; kb++) a += gcp[kb * 10 + j];
        csm[j] = a;
    }
    __syncthreads();
    if (tid < GTOK) {
        int tok = tid;
        float mu = vals[tok * 7] * (1.0f / ZD);
        float rs = rsqrtf(vals[tok * 7 + 1] * (1.0f / ZD) - mu * mu + 1e-5f);
        float lg[NPATH];
        float mx = -1e30f;
        #pragma unroll
        for (int pp = 0; pp < NPATH; pp++) {
            lg[pp] = rs * vals[tok * 7 + 2 + pp] - rs * mu * csm[pp] + csm[NPATH + pp] + gb[pp];
            mx = fmaxf(mx, lg[pp]);
        }
        float ssum = 0.f;
        #pragma unroll
        for (int pp = 0; pp < NPATH; pp++) { lg[pp] = expf(lg[pp] - mx); ssum += lg[pp]; }
        float inv = 1.0f / ssum;
        #pragma unroll
        for (int pp = 0; pp < NPATH; pp++) spi[tok][pp] = lg[pp] * inv;
        gmem_out[t0 + tok] = spi[tok][1] + spi[tok][2] + spi[tok][3] + spi[tok][4];
    }
    __syncthreads();

    float4* out4 = (float4*)out;
    #pragma unroll
    for (int lin = tid; lin < GTOK * (DDIM / 4); lin += GTHR) {
        int tok = lin >> 8, d4 = lin & 255;
        float o0 = 0.f, o1 = 0.f, o2 = 0.f, o3 = 0.f;
        #pragma unroll
        for (int pp = 0; pp < NPATH; pp++) {
            uint2 zc = z2s[tok * Z4PT + pp * 256 + d4];
            __half2 h01 = *reinterpret_cast<__half2*>(&zc.x);
            __half2 h23 = *reinterpret_cast<__half2*>(&zc.y);
            float2 f01 = __half22float2(h01);
            float2 f23 = __half22float2(h23);
            float ww = spi[tok][pp];
            o0 += ww * f01.x; o1 += ww * f01.y;
            o2 += ww * f23.x; o3 += ww * f23.y;
        }
        out4[(size_t)(t0 + tok) * 256 + d4] = make_float4(o0, o1, o2, o3);
    }
}
#define GATE_SMEM (GTOK * Z4PT * 8)      // 40 KB

// ---------------- launch ----------------
extern "C" void kernel_launch(void* const* d_in, const int* in_sizes, int n_in,
                              void* d_out, int out_size) {
    const float* x        = (const float*)d_in[0];
    const float* vt       = (const float*)d_in[1];
    const float* dts      = (const float*)d_in[2];
    const float* r_feat   = (const float*)d_in[3];
    const float* fln_g    = (const float*)d_in[4];
    const float* fln_b    = (const float*)d_in[5];
    const float* w1       = (const float*)d_in[6];
    const float* b1       = (const float*)d_in[7];
    const float* w2       = (const float*)d_in[8];
    const float* b2       = (const float*)d_in[9];
    const float* pg_g     = (const float*)d_in[10];
    const float* pg_b     = (const float*)d_in[11];
    const float* gw       = (const float*)d_in[12];
    const float* gb       = (const float*)d_in[13];

    float* out  = (float*)d_out;                  // [BT, D]
    float* gmem = out + (size_t)BT * DDIM;        // [BT]

    __half* abuf; cudaGetSymbolAddress((void**)&abuf, g_abuf);
    __half* hbuf; cudaGetSymbolAddress((void**)&hbuf, g_hbuf);
    __half* vtp;  cudaGetSymbolAddress((void**)&vtp,  g_vtp);
    __half* w1h;  cudaGetSymbolAddress((void**)&w1h,  g_w1h);
    __half* w2h;  cudaGetSymbolAddress((void**)&w2h,  g_w2h);
    float*  gwg;  cudaGetSymbolAddress((void**)&gwg,  g_gwg);
    float*  gcp;  cudaGetSymbolAddress((void**)&gcp,  g_gcp);

    cudaFuncSetAttribute(gemm_f16_kernel<0>, cudaFuncAttributeMaxDynamicSharedMemorySize, GEMM_SMEM);
    cudaFuncSetAttribute(gemm_f16_kernel<1>, cudaFuncAttributeMaxDynamicSharedMemorySize, GEMM_SMEM);
    cudaFuncSetAttribute(gate_kernel, cudaFuncAttributeMaxDynamicSharedMemorySize, GATE_SMEM);

    // K0: merged prep (weights cvt + gate-weight fold) + LN
    pre_kernel<<<NB_PRE, 256>>>(w1, w1h, w2, w2h, gw, pg_g, pg_b, gwg, gcp,
                                x, r_feat, fln_g, fln_b, abuf);

    // K1: h = fp16(gelu(A @ W1 + b1))
    {
        dim3 grid(HDIM / 128, BT / 128);
        gemm_f16_kernel<0><<<grid, 256, GEMM_SMEM>>>(abuf, w1h, b1, nullptr, hbuf, BT, HDIM, KF);
    }
    // K2: vt' = fp16(h @ W2 + b2 + vt)
    {
        dim3 grid(DDIM / 128, BT / 128);
        gemm_f16_kernel<1><<<grid, 256, GEMM_SMEM>>>(hbuf, w2h, b2, vt, vtp, BT, DDIM, HDIM);
    }
    // K3: gating + mix (folded LN, fp16 z cache, fp16 vtp, 4 CTAs/SM)
    gate_kernel<<<BT / GTOK, GTHR, GATE_SMEM>>>(vtp, dts, gwg, gcp, gb, out, gmem);
}

// round 17
// speedup vs baseline: 1.0354x; 1.0354x over previous
#include <cuda_runtime.h>
#include <cuda_fp16.h>
#include <math.h>
#include <stdint.h>

#define BT    8192      // B*T tokens
#define DDIM  1024
#define WRD   128
#define KF    1152      // D + WR
#define HDIM  4096
#define NPATH 5
#define ZD    5120      // NPATH * D

// ---------------- scratch (device globals; allocation-free) ----------------
__device__ __half g_abuf[BT * KF];                // LN(cat(x, r_feat)), fp16
__device__ __half g_hbuf[BT * HDIM];              // gelu(A@W1 + b1), fp16
__device__ __half g_vtp [BT * DDIM];              // vt + h@W2 + b2 (fp16)
__device__ __half g_w1h [KF * HDIM];              // w1 fp16 [K,N]
__device__ __half g_w2h [HDIM * DDIM];            // w2 fp16 [K,N]
__device__ __half g_gwg [NPATH * ZD];             // (pg_g * gate_w)^T [5, 5120] fp16
__device__ float  g_gcp [20 * 10];                // per-block partials of c1[5], c2[5]

// ---------------- helpers ----------------
__device__ __forceinline__ float tanh_fast(float x) {
    float t;
    asm("tanh.approx.f32 %0, %1;" : "=f"(t) : "f"(x));
    return t;
}
__device__ __forceinline__ float gelu_tanh(float v) {
    float t = tanh_fast(0.7978845608028654f * (v + 0.044715f * v * v * v));
    return 0.5f * v * (1.0f + t);
}
__device__ __forceinline__ uint32_t smem_u32(const void* p) {
    uint32_t a;
    asm("{ .reg .u64 t; cvta.to.shared.u64 t, %1; cvt.u32.u64 %0, t; }" : "=r"(a) : "l"(p));
    return a;
}
__device__ __forceinline__ void mma_f16(float* d, const uint32_t* a, const uint32_t* b) {
    asm volatile(
        "mma.sync.aligned.m16n8k16.row.col.f32.f16.f16.f32 "
        "{%0,%1,%2,%3}, {%4,%5,%6,%7}, {%8,%9}, {%0,%1,%2,%3};"
        : "+f"(d[0]), "+f"(d[1]), "+f"(d[2]), "+f"(d[3])
        : "r"(a[0]), "r"(a[1]), "r"(a[2]), "r"(a[3]),
          "r"(b[0]), "r"(b[1]));
}
__device__ __forceinline__ void ldsm_x4(uint32_t* r, uint32_t addr) {
    asm volatile("ldmatrix.sync.aligned.m8n8.x4.shared.b16 {%0,%1,%2,%3}, [%4];"
        : "=r"(r[0]), "=r"(r[1]), "=r"(r[2]), "=r"(r[3]) : "r"(addr));
}
__device__ __forceinline__ void ldsm_x4_t(uint32_t* r, uint32_t addr) {
    asm volatile("ldmatrix.sync.aligned.m8n8.x4.trans.shared.b16 {%0,%1,%2,%3}, [%4];"
        : "=r"(r[0]), "=r"(r[1]), "=r"(r[2]), "=r"(r[3]) : "r"(addr));
}
__device__ __forceinline__ void cp16(uint32_t dst, const void* src) {
    asm volatile("cp.async.cg.shared.global [%0], [%1], 16;" :: "r"(dst), "l"(src));
}
__device__ __forceinline__ void cp_commit() {
    asm volatile("cp.async.commit_group;" ::: "memory");
}
template <int N>
__device__ __forceinline__ void cp_wait() {
    asm volatile("cp.async.wait_group %0;" :: "n"(N) : "memory");
}

// ---------------- K0: merged pre-kernel -----------------------------------------------
#define N1F4 (KF * HDIM / 4)
#define N2F4 (HDIM * DDIM / 4)
#define NB_W ((N1F4 + N2F4) / 256)       // 8704 (exact)
#define NB_G 20                          // ZD / 256
#define LTOK 4
#define NB_L (BT / LTOK)                 // 2048
#define NB_PRE (NB_W + NB_G + NB_L)

__global__ __launch_bounds__(256)
void pre_kernel(const float* __restrict__ w1, __half* __restrict__ w1h,
                const float* __restrict__ w2, __half* __restrict__ w2h,
                const float* __restrict__ gw, const float* __restrict__ pg_g,
                const float* __restrict__ pg_b, __half* __restrict__ gwg,
                float* __restrict__ gcp,
                const float* __restrict__ x, const float* __restrict__ rf,
                const float* __restrict__ g, const float* __restrict__ b,
                __half* __restrict__ out) {
    const int blk = blockIdx.x;
    const int tid = threadIdx.x;

    if (blk < NB_W) {
        int i = blk * 256 + tid;
        const float4* src;
        uint2* dst;
        int idx;
        if (i < N1F4) { src = (const float4*)w1; dst = (uint2*)w1h; idx = i; }
        else          { src = (const float4*)w2; dst = (uint2*)w2h; idx = i - N1F4; }
        float4 v = src[idx];
        __half2 h01 = __floats2half2_rn(v.x, v.y);
        __half2 h23 = __floats2half2_rn(v.z, v.w);
        uint2 o;
        o.x = *reinterpret_cast<uint32_t*>(&h01);
        o.y = *reinterpret_cast<uint32_t*>(&h23);
        dst[idx] = o;
        return;
    }
    if (blk < NB_W + NB_G) {
        __shared__ float red[8][10];
        int kblk = blk - NB_W;
        int k = kblk * 256 + tid;
        float gk = pg_g[k], bk = pg_b[k];
        float c1l[NPATH], c2l[NPATH];
        #pragma unroll
        for (int p = 0; p < NPATH; p++) {
            float w = gw[(size_t)k * NPATH + p];
            __half gh = __float2half_rn(gk * w);
            gwg[p * ZD + k] = gh;
            c1l[p] = __half2float(gh);     // c1 from ROUNDED weights (exact fold)
            c2l[p] = bk * w;
        }
        int lane = tid & 31, wp = tid >> 5;
        #pragma unroll
        for (int p = 0; p < NPATH; p++) {
            #pragma unroll
            for (int o = 16; o > 0; o >>= 1) {
                c1l[p] += __shfl_down_sync(0xffffffffu, c1l[p], o);
                c2l[p] += __shfl_down_sync(0xffffffffu, c2l[p], o);
            }
        }
        if (lane == 0) {
            #pragma unroll
            for (int p = 0; p < NPATH; p++) {
                red[wp][p] = c1l[p];
                red[wp][p + NPATH] = c2l[p];
            }
        }
        __syncthreads();
        if (tid < 10) {
            float a = 0.f;
            #pragma unroll
            for (int ww = 0; ww < 8; ww++) a += red[ww][tid];
            gcp[kblk * 10 + tid] = a;
        }
        return;
    }

    // LN region: 4 tokens per block
    {
        const int t0 = (blk - NB_W - NB_G) * LTOK;
        __shared__ float red8[8][8];
        __shared__ float musm[LTOK], rssm[LTOK];
        const int lane = tid & 31, w = tid >> 5;
        const float4* x4  = (const float4*)x;
        const float4* rf4 = (const float4*)rf;
        const float4* g4  = (const float4*)g;
        const float4* b4  = (const float4*)b;
        const bool has2 = tid < 32;

        float4 gg0 = g4[tid], bb0 = b4[tid];
        float4 gg1, bb1;
        if (has2) { gg1 = g4[256 + tid]; bb1 = b4[256 + tid]; }

        float4 v0[LTOK], v1[LTOK];
        float ls[LTOK], lq[LTOK];
        #pragma unroll
        for (int tok = 0; tok < LTOK; tok++) {
            int t = t0 + tok;
            float4 a = x4[(size_t)t * 256 + tid];
            v0[tok] = a;
            float s = a.x + a.y + a.z + a.w;
            float q = a.x * a.x + a.y * a.y + a.z * a.z + a.w * a.w;
            if (has2) {
                float4 c = rf4[(size_t)t * 32 + tid];
                v1[tok] = c;
                s += c.x + c.y + c.z + c.w;
                q += c.x * c.x + c.y * c.y + c.z * c.z + c.w * c.w;
            }
            ls[tok] = s; lq[tok] = q;
        }
        #pragma unroll
        for (int tok = 0; tok < LTOK; tok++) {
            #pragma unroll
            for (int o = 16; o > 0; o >>= 1) {
                ls[tok] += __shfl_down_sync(0xffffffffu, ls[tok], o);
                lq[tok] += __shfl_down_sync(0xffffffffu, lq[tok], o);
            }
        }
        if (lane == 0) {
            #pragma unroll
            for (int tok = 0; tok < LTOK; tok++) {
                red8[w][tok] = ls[tok];
                red8[w][tok + 4] = lq[tok];
            }
        }
        __syncthreads();
        if (tid < 8) {
            float a = 0.f;
            #pragma unroll
            for (int ww = 0; ww < 8; ww++) a += red8[ww][tid];
            if (tid < 4) musm[tid] = a * (1.0f / KF);
            else         red8[0][tid] = a;
        }
        __syncthreads();
        if (tid < 4) {
            float mu = musm[tid];
            rssm[tid] = rsqrtf(red8[0][tid + 4] * (1.0f / KF) - mu * mu + 1e-5f);
        }
        __syncthreads();

        uint2* o4 = (uint2*)out;
        #pragma unroll
        for (int tok = 0; tok < LTOK; tok++) {
            float mu = musm[tok], rs = rssm[tok];
            float4 a = v0[tok];
            __half2 h01 = __floats2half2_rn((a.x - mu) * rs * gg0.x + bb0.x,
                                            (a.y - mu) * rs * gg0.y + bb0.y);
            __half2 h23 = __floats2half2_rn((a.z - mu) * rs * gg0.z + bb0.z,
                                            (a.w - mu) * rs * gg0.w + bb0.w);
            uint2 o;
            o.x = *reinterpret_cast<uint32_t*>(&h01);
            o.y = *reinterpret_cast<uint32_t*>(&h23);
            o4[(size_t)(t0 + tok) * (KF / 4) + tid] = o;
            if (has2) {
                float4 c = v1[tok];
                __half2 k01 = __floats2half2_rn((c.x - mu) * rs * gg1.x + bb1.x,
                                                (c.y - mu) * rs * gg1.y + bb1.y);
                __half2 k23 = __floats2half2_rn((c.z - mu) * rs * gg1.z + bb1.z,
                                                (c.w - mu) * rs * gg1.w + bb1.w);
                uint2 o2;
                o2.x = *reinterpret_cast<uint32_t*>(&k01);
                o2.y = *reinterpret_cast<uint32_t*>(&k23);
                o4[(size_t)(t0 + tok) * (KF / 4) + 256 + tid] = o2;
            }
        }
    }
}

// ---------------- fp16 mma.sync GEMM: CTA 128x128, warp 64x32, BK=64 ------------------
#define TS_H   72
#define TS_B   136
#define A_TILE_B (128 * TS_H * 2)
#define B_TILE_B (64 * TS_B * 2)
#define ST_B   (A_TILE_B + B_TILE_B)
#define NSTAGE 3
#define GEMM_SMEM (NSTAGE * ST_B)

__device__ __forceinline__ void load_a_tile(const __half* __restrict__ g, int row0, int K,
                                            int kt, uint32_t sm) {
    int tid = threadIdx.x;
    #pragma unroll
    for (int i = 0; i < 4; i++) {
        int lin = tid + i * 256;
        int row = lin >> 3, c8 = lin & 7;
        cp16(sm + (uint32_t)(row * TS_H + c8 * 8) * 2,
             &g[(size_t)(row0 + row) * K + kt + c8 * 8]);
    }
}
__device__ __forceinline__ void load_b_tile(const __half* __restrict__ g, int nb, int N,
                                            int kt, uint32_t sm) {
    int tid = threadIdx.x;
    #pragma unroll
    for (int i = 0; i < 4; i++) {
        int lin = tid + i * 256;
        int row = lin >> 4, c16 = lin & 15;
        cp16(sm + (uint32_t)(row * TS_B + c16 * 8) * 2,
             &g[(size_t)(kt + row) * N + nb + c16 * 8]);
    }
}

template <int EPI>
__global__ __launch_bounds__(256, 2)
void gemm_f16_kernel(const __half* __restrict__ A, const __half* __restrict__ Bkn,
                     const float* __restrict__ bias, const float* __restrict__ resid,
                     __half* __restrict__ Cout, int M, int N, int K) {
    extern __shared__ __half smh[];
    uint32_t sbase = smem_u32(smh);

    const int tid  = threadIdx.x;
    const int lane = tid & 31;
    const int warp = tid >> 5;
    const int wm = warp >> 2;
    const int wn = warp & 3;
    const int mb = blockIdx.y * 128;
    const int nb = blockIdx.x * 128;
    const int r = lane >> 2;
    const int c = lane & 3;

    uint32_t offA[4], offB[2];
    #pragma unroll
    for (int mi = 0; mi < 4; mi++) {
        int row = wm * 64 + mi * 16 + (lane & 15);
        offA[mi] = (uint32_t)(row * TS_H + ((lane >> 4) & 1) * 8) * 2;
    }
    #pragma unroll
    for (int np = 0; np < 2; np++) {
        int krow = ((lane >> 3) & 1) * 8 + (lane & 7);
        int ncol = wn * 32 + np * 16 + ((lane >> 4) & 1) * 8;
        offB[np] = (uint32_t)(krow * TS_B + ncol) * 2;
    }

    float acc[4][4][4];
    #pragma unroll
    for (int mi = 0; mi < 4; mi++)
        #pragma unroll
        for (int ni = 0; ni < 4; ni++)
            #pragma unroll
            for (int j = 0; j < 4; j++) acc[mi][ni][j] = 0.0f;

    const int S = K >> 6;

    load_a_tile(A,   mb, K, 0, sbase);
    load_b_tile(Bkn, nb, N, 0, sbase + A_TILE_B);
    cp_commit();
    if (S > 1) {
        load_a_tile(A,   mb, K, 64, sbase + ST_B);
        load_b_tile(Bkn, nb, N, 64, sbase + ST_B + A_TILE_B);
    }
    cp_commit();

    int p = 0;
    for (int s = 0; s < S; s++) {
        if (s < S - 1) cp_wait<1>(); else cp_wait<0>();
        __syncthreads();

        if (s + 2 < S) {
            int q = p + 2; if (q >= NSTAGE) q -= NSTAGE;
            load_a_tile(A,   mb, K, (s + 2) << 6, sbase + q * ST_B);
            load_b_tile(Bkn, nb, N, (s + 2) << 6, sbase + q * ST_B + A_TILE_B);
        }
        cp_commit();

        uint32_t abase = sbase + p * ST_B;
        uint32_t bbase = abase + A_TILE_B;

        #pragma unroll
        for (int kk = 0; kk < 4; kk++) {
            uint32_t koffA = (uint32_t)kk * 32;
            uint32_t koffB = (uint32_t)kk * (16 * TS_B * 2);
            uint32_t afr[4][4];
            uint32_t bfr[2][4];
            #pragma unroll
            for (int mi = 0; mi < 4; mi++) ldsm_x4(afr[mi], abase + offA[mi] + koffA);
            #pragma unroll
            for (int np = 0; np < 2; np++) ldsm_x4_t(bfr[np], bbase + offB[np] + koffB);
            #pragma unroll
            for (int mi = 0; mi < 4; mi++)
                #pragma unroll
                for (int ni = 0; ni < 4; ni++)
                    mma_f16(acc[mi][ni], afr[mi], &bfr[ni >> 1][(ni & 1) * 2]);
        }
        p++; if (p >= NSTAGE) p -= NSTAGE;
    }
    __syncthreads();

    #pragma unroll
    for (int mi = 0; mi < 4; mi++) {
        int row0 = mb + wm * 64 + mi * 16 + r;
        #pragma unroll
        for (int ni = 0; ni < 4; ni++) {
            int col0 = nb + wn * 32 + ni * 8 + 2 * c;
            float bs0 = bias[col0], bs1 = bias[col0 + 1];
            #pragma unroll
            for (int half = 0; half < 2; half++) {
                int row = row0 + half * 8;
                float v0 = acc[mi][ni][half * 2 + 0] + bs0;
                float v1 = acc[mi][ni][half * 2 + 1] + bs1;
                __half2 hv;
                if (EPI == 0) {
                    hv = __floats2half2_rn(gelu_tanh(v0), gelu_tanh(v1));
                } else {
                    float2 rv = *reinterpret_cast<const float2*>(&resid[(size_t)row * N + col0]);
                    hv = __floats2half2_rn(v0 + rv.x, v1 + rv.y);
                }
                *reinterpret_cast<__half2*>(&Cout[(size_t)row * N + col0]) = hv;
            }
        }
    }
}

// ---------------- K3: path gating, folded-LN logits (R15 structure, fp16 gwg) ---------
#define GTOK 4
#define GTHR 256
#define Z4PT (ZD / 4)
__global__ __launch_bounds__(GTHR)
void gate_kernel(const __half* __restrict__ vtp, const float* __restrict__ dts,
                 const __half* __restrict__ gwg, const float* __restrict__ gcp,
                 const float* __restrict__ gb,
                 float* __restrict__ out, float* __restrict__ gmem_out) {
    extern __shared__ uint2 z2s[];           // [GTOK][Z4PT] fp16x4 = 40 KB
    __shared__ float red[8][28];             // [warp][tok*7 + stat]
    __shared__ float vals[28];
    __shared__ float csm[10];                // c1[5], c2[5]
    __shared__ float spi[GTOK][NPATH];

    const int tid = threadIdx.x;
    const int lane = tid & 31;
    const int w = tid >> 5;
    const int t0 = blockIdx.x * GTOK;

    const uint2*  vtp2 = (const uint2*)vtp;      // 4 halfs per uint2
    const float4* dts4 = (const float4*)dts;
    const uint2*  gwg2 = (const uint2*)gwg;      // [5][Z4PT] fp16x4

    float st[GTOK][7];   // [tok][0]=sum [1]=sq [2..6]=dot_p
    #pragma unroll
    for (int tok = 0; tok < GTOK; tok++)
        #pragma unroll
        for (int j = 0; j < 7; j++) st[tok][j] = 0.f;

    // single pass: load z -> fp16 smem, stats (fp32), folded dot products (fp32)
    for (int i4 = tid; i4 < Z4PT; i4 += GTHR) {
        float4 gwf[NPATH];
        #pragma unroll
        for (int pp = 0; pp < NPATH; pp++) {
            uint2 gq = gwg2[pp * Z4PT + i4];
            __half2 g01 = *reinterpret_cast<__half2*>(&gq.x);
            __half2 g23 = *reinterpret_cast<__half2*>(&gq.y);
            float2 f01 = __half22float2(g01);
            float2 f23 = __half22float2(g23);
            gwf[pp] = make_float4(f01.x, f01.y, f23.x, f23.y);
        }
        int p = i4 >> 8, d4 = i4 & 255;
        #pragma unroll
        for (int tok = 0; tok < GTOK; tok++) {
            int t = t0 + tok;
            float4 v;
            uint2 zc;
            if (p == 0) {
                zc = vtp2[(size_t)t * 256 + d4];
                __half2 h01 = *reinterpret_cast<__half2*>(&zc.x);
                __half2 h23 = *reinterpret_cast<__half2*>(&zc.y);
                float2 f01 = __half22float2(h01);
                float2 f23 = __half22float2(h23);
                v = make_float4(f01.x, f01.y, f23.x, f23.y);
            } else {
                v = dts4[((size_t)(p - 1) * BT + t) * 256 + d4];
                __half2 h01 = __floats2half2_rn(v.x, v.y);
                __half2 h23 = __floats2half2_rn(v.z, v.w);
                zc.x = *reinterpret_cast<uint32_t*>(&h01);
                zc.y = *reinterpret_cast<uint32_t*>(&h23);
            }
            z2s[tok * Z4PT + i4] = zc;
            st[tok][0] += v.x + v.y + v.z + v.w;
            st[tok][1] += v.x * v.x + v.y * v.y + v.z * v.z + v.w * v.w;
            #pragma unroll
            for (int pp = 0; pp < NPATH; pp++)
                st[tok][2 + pp] += v.x * gwf[pp].x + v.y * gwf[pp].y
                                 + v.z * gwf[pp].z + v.w * gwf[pp].w;
        }
    }
    // warp reduce all 28
    #pragma unroll
    for (int tok = 0; tok < GTOK; tok++)
        #pragma unroll
        for (int j = 0; j < 7; j++) {
            float v = st[tok][j];
            #pragma unroll
            for (int o = 16; o > 0; o >>= 1) v += __shfl_down_sync(0xffffffffu, v, o);
            if (lane == 0) red[w][tok * 7 + j] = v;
        }
    __syncthreads();
    if (tid < 28) {
        float a = 0.f;
        #pragma unroll
        for (int ww = 0; ww < 8; ww++) a += red[ww][tid];
        vals[tid] = a;
    }
    if (tid >= 32 && tid < 42) {
        int j = tid - 32;
        float a = 0.f;
        #pragma unroll
        for (int kb = 0; kb < 20; kb++) a += gcp[kb * 10 + j];
        csm[j] = a;
    }
    __syncthreads();
    if (tid < GTOK) {
        int tok = tid;
        float mu = vals[tok * 7] * (1.0f / ZD);
        float rs = rsqrtf(vals[tok * 7 + 1] * (1.0f / ZD) - mu * mu + 1e-5f);
        float lg[NPATH];
        float mx = -1e30f;
        #pragma unroll
        for (int pp = 0; pp < NPATH; pp++) {
            lg[pp] = rs * vals[tok * 7 + 2 + pp] - rs * mu * csm[pp] + csm[NPATH + pp] + gb[pp];
            mx = fmaxf(mx, lg[pp]);
        }
        float ssum = 0.f;
        #pragma unroll
        for (int pp = 0; pp < NPATH; pp++) { lg[pp] = expf(lg[pp] - mx); ssum += lg[pp]; }
        float inv = 1.0f / ssum;
        #pragma unroll
        for (int pp = 0; pp < NPATH; pp++) spi[tok][pp] = lg[pp] * inv;
        gmem_out[t0 + tok] = spi[tok][1] + spi[tok][2] + spi[tok][3] + spi[tok][4];
    }
    __syncthreads();

    float4* out4 = (float4*)out;
    #pragma unroll
    for (int lin = tid; lin < GTOK * (DDIM / 4); lin += GTHR) {
        int tok = lin >> 8, d4 = lin & 255;
        float o0 = 0.f, o1 = 0.f, o2 = 0.f, o3 = 0.f;
        #pragma unroll
        for (int pp = 0; pp < NPATH; pp++) {
            uint2 zc = z2s[tok * Z4PT + pp * 256 + d4];
            __half2 h01 = *reinterpret_cast<__half2*>(&zc.x);
            __half2 h23 = *reinterpret_cast<__half2*>(&zc.y);
            float2 f01 = __half22float2(h01);
            float2 f23 = __half22float2(h23);
            float ww = spi[tok][pp];
            o0 += ww * f01.x; o1 += ww * f01.y;
            o2 += ww * f23.x; o3 += ww * f23.y;
        }
        out4[(size_t)(t0 + tok) * 256 + d4] = make_float4(o0, o1, o2, o3);
    }
}
#define GATE_SMEM (GTOK * Z4PT * 8)      // 40 KB

// ---------------- launch ----------------
extern "C" void kernel_launch(void* const* d_in, const int* in_sizes, int n_in,
                              void* d_out, int out_size) {
    const float* x        = (const float*)d_in[0];
    const float* vt       = (const float*)d_in[1];
    const float* dts      = (const float*)d_in[2];
    const float* r_feat   = (const float*)d_in[3];
    const float* fln_g    = (const float*)d_in[4];
    const float* fln_b    = (const float*)d_in[5];
    const float* w1       = (const float*)d_in[6];
    const float* b1       = (const float*)d_in[7];
    const float* w2       = (const float*)d_in[8];
    const float* b2       = (const float*)d_in[9];
    const float* pg_g     = (const float*)d_in[10];
    const float* pg_b     = (const float*)d_in[11];
    const float* gw       = (const float*)d_in[12];
    const float* gb       = (const float*)d_in[13];

    float* out  = (float*)d_out;                  // [BT, D]
    float* gmem = out + (size_t)BT * DDIM;        // [BT]

    __half* abuf; cudaGetSymbolAddress((void**)&abuf, g_abuf);
    __half* hbuf; cudaGetSymbolAddress((void**)&hbuf, g_hbuf);
    __half* vtp;  cudaGetSymbolAddress((void**)&vtp,  g_vtp);
    __half* w1h;  cudaGetSymbolAddress((void**)&w1h,  g_w1h);
    __half* w2h;  cudaGetSymbolAddress((void**)&w2h,  g_w2h);
    __half* gwg;  cudaGetSymbolAddress((void**)&gwg,  g_gwg);
    float*  gcp;  cudaGetSymbolAddress((void**)&gcp,  g_gcp);

    cudaFuncSetAttribute(gemm_f16_kernel<0>, cudaFuncAttributeMaxDynamicSharedMemorySize, GEMM_SMEM);
    cudaFuncSetAttribute(gemm_f16_kernel<1>, cudaFuncAttributeMaxDynamicSharedMemorySize, GEMM_SMEM);
    cudaFuncSetAttribute(gate_kernel, cudaFuncAttributeMaxDynamicSharedMemorySize, GATE_SMEM);

    // K0: merged prep (weights cvt + gate-weight fold) + LN
    pre_kernel<<<NB_PRE, 256>>>(w1, w1h, w2, w2h, gw, pg_g, pg_b, gwg, gcp,
                                x, r_feat, fln_g, fln_b, abuf);

    // K1: h = fp16(gelu(A @ W1 + b1))
    {
        dim3 grid(HDIM / 128, BT / 128);
        gemm_f16_kernel<0><<<grid, 256, GEMM_SMEM>>>(abuf, w1h, b1, nullptr, hbuf, BT, HDIM, KF);
    }
    // K2: vt' = fp16(h @ W2 + b2 + vt)
    {
        dim3 grid(DDIM / 128, BT / 128);
        gemm_f16_kernel<1><<<grid, 256, GEMM_SMEM>>>(hbuf, w2h, b2, vt, vtp, BT, DDIM, HDIM);
    }
    // K3: gating + mix (folded LN, fp16 z cache, fp16 vtp, fp16 gwg)
    gate_kernel<<<BT / GTOK, GTHR, GATE_SMEM>>>(vtp, dts, gwg, gcp, gb, out, gmem);
}